// round 13
// baseline (speedup 1.0000x reference)
#include <cuda_runtime.h>
#include <stdint.h>
#include <math.h>

#define NT 1024
#define CA 768
#define CS 384
#define CZ 128
#define NH 16
#define HD 48
#define LNEPS 1e-5f

// ---------------- scratch (static device globals; no runtime allocation) ----------------
__device__ float g_sln1[NT*CS];
__device__ float g_sln2[NT*CS];
__device__ float g_aln [NT*CA];
__device__ float g_t1  [NT*CA];
__device__ float g_t2  [NT*CA];
__device__ float g_x   [NT*CA];
__device__ float g_q   [NT*CA];
__device__ float g_k   [NT*CA];
__device__ float g_v   [NT*CA];
__device__ float g_g   [NT*CA];
__device__ float g_kT  [NH*HD*NT];
__device__ float g_scores[(long)NH*NT*NT];
__device__ float g_o   [NT*CA];
__device__ float g_amid[NT*CA];
__device__ float g_swl [NT*CA];
__device__ float g_attn[NT*CA];
__device__ float g_aln2[NT*CA];
__device__ float g_ff1 [NT*2*CA];
__device__ float g_ff2 [NT*2*CA];
__device__ float g_bb  [NT*CA];
__device__ float g_sws [NT*CA];

__device__ __forceinline__ float wsum(float v){
    v += __shfl_xor_sync(0xffffffffu, v, 16);
    v += __shfl_xor_sync(0xffffffffu, v, 8);
    v += __shfl_xor_sync(0xffffffffu, v, 4);
    v += __shfl_xor_sync(0xffffffffu, v, 2);
    v += __shfl_xor_sync(0xffffffffu, v, 1);
    return v;
}
__device__ __forceinline__ float wmax(float v){
    v = fmaxf(v, __shfl_xor_sync(0xffffffffu, v, 16));
    v = fmaxf(v, __shfl_xor_sync(0xffffffffu, v, 8));
    v = fmaxf(v, __shfl_xor_sync(0xffffffffu, v, 4));
    v = fmaxf(v, __shfl_xor_sync(0xffffffffu, v, 2));
    v = fmaxf(v, __shfl_xor_sync(0xffffffffu, v, 1));
    return v;
}
__device__ __forceinline__ float sigm(float x){ return 1.0f/(1.0f + __expf(-x)); }

__device__ __forceinline__ void cpa16(unsigned dst, const float* src, int szbytes){
    asm volatile("cp.async.ca.shared.global [%0], [%1], 16, %2;"
                 :: "r"(dst), "l"(src), "r"(szbytes));
}
__device__ __forceinline__ void cpa_commit(){ asm volatile("cp.async.commit_group;"); }
template<int N_> __device__ __forceinline__ void cpa_wait(){
    asm volatile("cp.async.wait_group %0;" :: "n"(N_));
}

// ---------------- tf32 tensor-core GEMM: C = alpha*(A@B + bias) (+C) ----------------
// Block tile 128xBN x16, 8 warps, cp.async 3-stage pipeline. A row-major [M,K],
// B row-major [K,N], C row-major [M,N], batched via grid.z.
// Requires: K%16==0, M%128==0, 16B-aligned A/B bases, lda/ldb%4==0. N guarded.
// fp32 bits are fed to mma.tf32 directly (HW truncation).
#define SA 20
template<int BN>
__global__ __launch_bounds__(256) void tgemm_k(
    const float* __restrict__ A, int lda, long sA_,
    const float* __restrict__ B, int ldb, long sB_,
    float* __restrict__ C, int ldc, long sC_,
    int M, int N, int K,
    const float* __restrict__ bias, float alpha, int accum)
{
    constexpr int SBS = BN + 8;          // % 32 == 8 -> conflict-free fragment loads
    constexpr int WC  = BN / 32;         // warps along N
    constexpr int WTM = (WC == 4) ? 64 : 32;
    constexpr int MI  = WTM / 16;
    constexpr int ST  = 3;
    __shared__ float As[ST][128*SA];
    __shared__ float Bs[ST][16*SBS];

    int bz = blockIdx.z;
    A += (long)bz * sA_; B += (long)bz * sB_; C += (long)bz * sC_;
    int bm = blockIdx.y << 7, bn = blockIdx.x * BN;
    int tid = threadIdx.x;
    int lane = tid & 31, warp = tid >> 5;
    int wn = (warp % WC) * 32;
    int wm = (warp / WC) * WTM;
    int g = lane >> 2, tq = lane & 3;

    float acc[MI][4][4];
    #pragma unroll
    for (int mi = 0; mi < MI; mi++)
        #pragma unroll
        for (int nj = 0; nj < 4; nj++)
            #pragma unroll
            for (int r = 0; r < 4; r++) acc[mi][nj][r] = 0.0f;

    int KT = K >> 4;

    auto issue = [&](int s, int k0) {
        // A: 128 rows x 16 k = 512 float4, 2 per thread
        #pragma unroll
        for (int i = 0; i < 2; i++) {
            int idx = tid + (i << 8);
            int row = idx >> 2, kq = (idx & 3) << 2;
            unsigned dst = (unsigned)__cvta_generic_to_shared(&As[s][row*SA + kq]);
            cpa16(dst, A + (long)(bm + row) * lda + k0 + kq, 16);
        }
        // B: 16 rows x BN = BN*4 float4, BN/64 per thread
        #pragma unroll
        for (int i = 0; i < BN/64; i++) {
            int idx = tid + (i << 8);
            int row = idx / (BN/4), col = (idx % (BN/4)) << 2;
            unsigned dst = (unsigned)__cvta_generic_to_shared(&Bs[s][row*SBS + col]);
            cpa16(dst, B + (long)(k0 + row) * ldb + bn + col, (bn + col < N) ? 16 : 0);
        }
    };

    #pragma unroll
    for (int s = 0; s < ST-1; s++) {
        if (s < KT) issue(s, s << 4);
        cpa_commit();
    }

    for (int kt = 0; kt < KT; kt++) {
        cpa_wait<ST-2>();
        __syncthreads();
        int pre = kt + ST - 1;
        if (pre < KT) issue(pre % ST, pre << 4);
        cpa_commit();

        int buf = kt % ST;
        #pragma unroll
        for (int ks = 0; ks < 16; ks += 8) {
            unsigned af[MI][4], bf[4][2];
            #pragma unroll
            for (int mi = 0; mi < MI; mi++) {
                int m0 = (wm + (mi << 4) + g) * SA + ks + tq;
                af[mi][0] = __float_as_uint(As[buf][m0]);
                af[mi][1] = __float_as_uint(As[buf][m0 + 8*SA]);
                af[mi][2] = __float_as_uint(As[buf][m0 + 4]);
                af[mi][3] = __float_as_uint(As[buf][m0 + 8*SA + 4]);
            }
            #pragma unroll
            for (int nj = 0; nj < 4; nj++) {
                int n0 = (ks + tq) * SBS + wn + (nj << 3) + g;
                bf[nj][0] = __float_as_uint(Bs[buf][n0]);
                bf[nj][1] = __float_as_uint(Bs[buf][n0 + 4*SBS]);
            }
            #pragma unroll
            for (int mi = 0; mi < MI; mi++)
                #pragma unroll
                for (int nj = 0; nj < 4; nj++)
                    asm volatile(
                        "mma.sync.aligned.m16n8k8.row.col.f32.tf32.tf32.f32 "
                        "{%0,%1,%2,%3}, {%4,%5,%6,%7}, {%8,%9}, {%0,%1,%2,%3};"
                        : "+f"(acc[mi][nj][0]), "+f"(acc[mi][nj][1]),
                          "+f"(acc[mi][nj][2]), "+f"(acc[mi][nj][3])
                        : "r"(af[mi][0]), "r"(af[mi][1]), "r"(af[mi][2]), "r"(af[mi][3]),
                          "r"(bf[nj][0]), "r"(bf[nj][1]));
        }
    }

    #pragma unroll
    for (int mi = 0; mi < MI; mi++) {
        int r0 = bm + wm + (mi << 4) + g;
        int r1 = r0 + 8;
        #pragma unroll
        for (int nj = 0; nj < 4; nj++) {
            int col = bn + wn + (nj << 3) + (tq << 1);
            #pragma unroll
            for (int half = 0; half < 2; half++) {
                int cc = col + half;
                if (cc >= N) continue;
                float bia = bias ? bias[cc] : 0.0f;
                {
                    float v = (acc[mi][nj][half] + bia) * alpha;
                    long ci = (long)r0 * ldc + cc;
                    if (accum) v += C[ci];
                    C[ci] = v;
                }
                {
                    float v = (acc[mi][nj][2+half] + bia) * alpha;
                    long ci = (long)r1 * ldc + cc;
                    if (accum) v += C[ci];
                    C[ci] = v;
                }
            }
        }
    }
}

// ---------------- row LayerNorm (optional affine) ----------------
__global__ __launch_bounds__(256) void ln_rows_k(
    const float* __restrict__ in, float* __restrict__ out,
    const float* __restrict__ gam, const float* __restrict__ bet, int cols)
{
    long row = blockIdx.x;
    const float* x = in + row * cols;
    float* y = out + row * cols;
    float s1 = 0.f, s2 = 0.f;
    for (int c = threadIdx.x; c < cols; c += blockDim.x) {
        float v = x[c]; s1 += v; s2 += v * v;
    }
    __shared__ float r1[8], r2[8];
    int w = threadIdx.x >> 5, l = threadIdx.x & 31;
    s1 = wsum(s1); s2 = wsum(s2);
    if (l == 0) { r1[w] = s1; r2[w] = s2; }
    __syncthreads();
    __shared__ float sm, si;
    if (threadIdx.x == 0) {
        float a = 0.f, b = 0.f;
        int nw = blockDim.x >> 5;
        for (int i = 0; i < nw; i++) { a += r1[i]; b += r2[i]; }
        float mean = a / cols;
        float var = b / cols - mean * mean;
        sm = mean; si = rsqrtf(var + LNEPS);
    }
    __syncthreads();
    float mean = sm, inv = si;
    for (int c = threadIdx.x; c < cols; c += blockDim.x) {
        float v = (x[c] - mean) * inv;
        if (gam) v = v * gam[c] + bet[c];
        y[c] = v;
    }
}

// ---------------- fused z: LN + Wz projection -> scores bias, plus z copy-out ----------------
__global__ __launch_bounds__(256) void z_fused_k(
    const float* __restrict__ z, const float* __restrict__ zg, const float* __restrict__ zb,
    const float* __restrict__ Wz, float* __restrict__ scores, float* __restrict__ out_z)
{
    __shared__ float sW[NH * CZ];      // transposed: sW[h*128 + c]
    __shared__ float sg[CZ], sb[CZ];
    __shared__ float sbias[NH][8];
    int tid = threadIdx.x;
    for (int i = tid; i < NH * CZ; i += 256) {
        int c = i >> 4, h = i & 15;          // Wz is [128,16] row-major: Wz[c*16+h]
        sW[h * CZ + c] = Wz[i];
    }
    if (tid < CZ) { sg[tid] = zg[tid]; sb[tid] = zb[tid]; }
    __syncthreads();

    int w = tid >> 5, lane = tid & 31;
    long r = (long)blockIdx.x * 8 + w;       // z row index, r = q*1024 + kk
    const float* zr = z + r * CZ;
    int c0 = lane * 4;
    float4 xv = *(const float4*)(zr + c0);
    float s1 = xv.x + xv.y + xv.z + xv.w;
    float s2 = xv.x*xv.x + xv.y*xv.y + xv.z*xv.z + xv.w*xv.w;
    s1 = wsum(s1); s2 = wsum(s2);
    float mean = s1 * (1.0f / CZ);
    float inv = rsqrtf(s2 * (1.0f / CZ) - mean * mean + LNEPS);
    float y0 = (xv.x - mean) * inv * sg[c0+0] + sb[c0+0];
    float y1 = (xv.y - mean) * inv * sg[c0+1] + sb[c0+1];
    float y2 = (xv.z - mean) * inv * sg[c0+2] + sb[c0+2];
    float y3 = (xv.w - mean) * inv * sg[c0+3] + sb[c0+3];
    #pragma unroll
    for (int h = 0; h < NH; h++) {
        const float* wh = sW + h * CZ + c0;
        float p = y0*wh[0] + y1*wh[1] + y2*wh[2] + y3*wh[3];
        p = wsum(p);
        if (lane == 0) sbias[h][w] = p;
    }
    *(float4*)(out_z + r * CZ + c0) = xv;
    __syncthreads();
    if (tid < NH * 8) {
        int h = tid >> 3, wi = tid & 7;
        long rr = (long)blockIdx.x * 8 + wi;
        long q = rr >> 10, kk = rr & 1023;
        scores[((long)h * NT + q) * NT + kk] = sbias[h][wi];
    }
}

// ---------------- pack k -> kT[h][d][j] ----------------
__global__ void pack_kT_k(const float* __restrict__ k, float* __restrict__ kT) {
    int idx = blockIdx.x * blockDim.x + threadIdx.x;
    if (idx < NH * HD * NT) {
        int j = idx & (NT - 1);
        int d = (idx >> 10) % HD;
        int h = idx / (HD * NT);
        kT[idx] = k[(long)j * CA + h * HD + d];
    }
}

// ---------------- softmax over last dim (1024), in-place ----------------
__global__ __launch_bounds__(256) void softmax_k(float* __restrict__ sc) {
    long row = blockIdx.x;
    float* p = sc + row * NT;
    float4 v = *(float4*)(p + threadIdx.x * 4);
    float m = fmaxf(fmaxf(v.x, v.y), fmaxf(v.z, v.w));
    __shared__ float r[8];
    int w = threadIdx.x >> 5, l = threadIdx.x & 31;
    m = wmax(m);
    if (l == 0) r[w] = m;
    __syncthreads();
    __shared__ float bm, bs;
    if (threadIdx.x == 0) {
        float mm = r[0];
        for (int i = 1; i < 8; i++) mm = fmaxf(mm, r[i]);
        bm = mm;
    }
    __syncthreads();
    m = bm;
    float e0 = __expf(v.x - m), e1 = __expf(v.y - m), e2 = __expf(v.z - m), e3 = __expf(v.w - m);
    float s = e0 + e1 + e2 + e3;
    s = wsum(s);
    if (l == 0) r[w] = s;
    __syncthreads();
    if (threadIdx.x == 0) {
        float ss = 0.f;
        for (int i = 0; i < 8; i++) ss += r[i];
        bs = 1.0f / ss;
    }
    __syncthreads();
    float inv = bs;
    *(float4*)(p + threadIdx.x * 4) = make_float4(e0*inv, e1*inv, e2*inv, e3*inv);
}

// ---------------- elementwise kernels ----------------
__global__ void combine_adaln_k(const float* __restrict__ g1, const float* __restrict__ gb,
                                const float* __restrict__ g2, const float* __restrict__ aln,
                                float* __restrict__ out, int total, int cols) {
    int i = blockIdx.x * blockDim.x + threadIdx.x;
    if (i < total) {
        int c = i % cols;
        out[i] = sigm(g1[i] + gb[c]) * aln[i] + g2[i];
    }
}
__global__ void gate_k(float* __restrict__ o, const float* __restrict__ g, int total) {
    int i = blockIdx.x * blockDim.x + threadIdx.x;
    if (i < total) o[i] *= sigm(g[i]);
}
__global__ void attnout_k(const float* __restrict__ swl, const float* __restrict__ amid,
                          const float* __restrict__ a, float* __restrict__ out, int total) {
    int i = blockIdx.x * blockDim.x + threadIdx.x;
    if (i < total) out[i] = sigm(swl[i]) * amid[i] + a[i];
}
__global__ void swiglu_k(float* __restrict__ f1, const float* __restrict__ f2, int total) {
    int i = blockIdx.x * blockDim.x + threadIdx.x;
    if (i < total) {
        float v = f1[i];
        f1[i] = v * sigm(v) * f2[i];
    }
}
__global__ void final_k(const float* __restrict__ sws, const float* __restrict__ bb,
                        const float* __restrict__ attn, float* __restrict__ out, int total) {
    int i = blockIdx.x * blockDim.x + threadIdx.x;
    if (i < total) out[i] = sigm(sws[i]) * bb[i] + attn[i];
}

// ---------------- host ----------------
static void gemm(const float* A, int lda, long sA_, const float* B, int ldb, long sB_,
                 float* C, int ldc, long sC_, int M, int N, int K, int batch,
                 const float* bias, float alpha, int accum) {
    int my = (M + 127) / 128;
    if (N % 128 == 0 && (long)(N / 128) * my * batch >= 120) {
        dim3 grid(N / 128, my, batch);
        tgemm_k<128><<<grid, 256>>>(A, lda, sA_, B, ldb, sB_, C, ldc, sC_, M, N, K, bias, alpha, accum);
    } else {
        dim3 grid((N + 63) / 64, my, batch);
        tgemm_k<64><<<grid, 256>>>(A, lda, sA_, B, ldb, sB_, C, ldc, sC_, M, N, K, bias, alpha, accum);
    }
}

extern "C" void kernel_launch(void* const* d_in, const int* in_sizes, int n_in,
                              void* d_out, int out_size) {
    const float* a      = (const float*)d_in[0];
    const float* s      = (const float*)d_in[1];
    const float* z      = (const float*)d_in[2];
    const float* a1_g   = (const float*)d_in[3];
    const float* a1_b   = (const float*)d_in[4];
    const float* a1_sgW = (const float*)d_in[5];
    const float* a1_sgb = (const float*)d_in[6];
    const float* a1_sbW = (const float*)d_in[7];
    const float* Wq     = (const float*)d_in[8];
    const float* bq     = (const float*)d_in[9];
    const float* Wk     = (const float*)d_in[10];
    const float* Wv     = (const float*)d_in[11];
    const float* Wg     = (const float*)d_in[12];
    const float* Wo     = (const float*)d_in[13];
    const float* bo     = (const float*)d_in[14];
    const float* zg     = (const float*)d_in[15];
    const float* zb     = (const float*)d_in[16];
    const float* Wz     = (const float*)d_in[17];
    const float* Wlast  = (const float*)d_in[18];
    const float* blast  = (const float*)d_in[19];
    const float* a2_g   = (const float*)d_in[20];
    const float* a2_b   = (const float*)d_in[21];
    const float* a2_sgW = (const float*)d_in[22];
    const float* a2_sgb = (const float*)d_in[23];
    const float* a2_sbW = (const float*)d_in[24];
    const float* W1     = (const float*)d_in[25];
    const float* W2     = (const float*)d_in[26];
    const float* Wb     = (const float*)d_in[27];
    const float* Ws     = (const float*)d_in[28];
    const float* bs     = (const float*)d_in[29];

    float* out   = (float*)d_out;
    float* out_a = out;                                  // 1024*768
    float* out_s = out + NT * CA;                        // 1024*384
    float* out_z = out + NT * CA + NT * CS;              // 1024*1024*128

    float *p_sln1, *p_sln2, *p_aln, *p_t1, *p_t2, *p_x, *p_q, *p_k, *p_v, *p_g;
    float *p_kT, *p_scores, *p_o, *p_amid, *p_swl, *p_attn, *p_aln2, *p_ff1, *p_ff2, *p_bb, *p_sws;
    cudaGetSymbolAddress((void**)&p_sln1, g_sln1);
    cudaGetSymbolAddress((void**)&p_sln2, g_sln2);
    cudaGetSymbolAddress((void**)&p_aln,  g_aln);
    cudaGetSymbolAddress((void**)&p_t1,   g_t1);
    cudaGetSymbolAddress((void**)&p_t2,   g_t2);
    cudaGetSymbolAddress((void**)&p_x,    g_x);
    cudaGetSymbolAddress((void**)&p_q,    g_q);
    cudaGetSymbolAddress((void**)&p_k,    g_k);
    cudaGetSymbolAddress((void**)&p_v,    g_v);
    cudaGetSymbolAddress((void**)&p_g,    g_g);
    cudaGetSymbolAddress((void**)&p_kT,   g_kT);
    cudaGetSymbolAddress((void**)&p_scores, g_scores);
    cudaGetSymbolAddress((void**)&p_o,    g_o);
    cudaGetSymbolAddress((void**)&p_amid, g_amid);
    cudaGetSymbolAddress((void**)&p_swl,  g_swl);
    cudaGetSymbolAddress((void**)&p_attn, g_attn);
    cudaGetSymbolAddress((void**)&p_aln2, g_aln2);
    cudaGetSymbolAddress((void**)&p_ff1,  g_ff1);
    cudaGetSymbolAddress((void**)&p_ff2,  g_ff2);
    cudaGetSymbolAddress((void**)&p_bb,   g_bb);
    cudaGetSymbolAddress((void**)&p_sws,  g_sws);

    const int EW = NT * CA;            // 786432
    const int EWB = (EW + 255) / 256;
    const float qscale = rsqrtf((float)HD);

    // pair bias + z passthrough (memory-bound; launch first)
    z_fused_k<<<(NT * NT) / 8, 256>>>(z, zg, zb, Wz, p_scores, out_z);
    cudaMemcpyAsync(out_s, s, (size_t)NT * CS * sizeof(float), cudaMemcpyDeviceToDevice, 0);

    // adaLN 1
    ln_rows_k<<<NT, 256>>>(s, p_sln1, a1_g, a1_b, CS);
    ln_rows_k<<<NT, 256>>>(a, p_aln, nullptr, nullptr, CA);
    gemm(p_sln1, CS, 0, a1_sgW, CA, 0, p_t1, CA, 0, NT, CA, CS, 1, nullptr, 1.f, 0);
    gemm(p_sln1, CS, 0, a1_sbW, CA, 0, p_t2, CA, 0, NT, CA, CS, 1, nullptr, 1.f, 0);
    combine_adaln_k<<<EWB, 256>>>(p_t1, a1_sgb, p_t2, p_aln, p_x, EW, CA);

    // projections
    gemm(p_x, CA, 0, Wq, CA, 0, p_q, CA, 0, NT, CA, CA, 1, bq, qscale, 0);
    gemm(p_x, CA, 0, Wk, CA, 0, p_k, CA, 0, NT, CA, CA, 1, nullptr, 1.f, 0);
    gemm(p_x, CA, 0, Wv, CA, 0, p_v, CA, 0, NT, CA, CA, 1, nullptr, 1.f, 0);
    gemm(p_x, CA, 0, Wg, CA, 0, p_g, CA, 0, NT, CA, CA, 1, nullptr, 1.f, 0);
    pack_kT_k<<<(NH * HD * NT + 255) / 256, 256>>>(p_k, p_kT);

    // attention: scores = q@kT + bias (bias already in scores), softmax, o = P@v
    gemm(p_q, CA, HD, p_kT, NT, (long)HD * NT, p_scores, NT, (long)NT * NT,
         NT, NT, HD, NH, nullptr, 1.f, 1);
    softmax_k<<<NH * NT, 256>>>(p_scores);
    gemm(p_scores, NT, (long)NT * NT, p_v, CA, HD, p_o, CA, HD,
         NT, HD, NT, NH, nullptr, 1.f, 0);
    gate_k<<<EWB, 256>>>(p_o, p_g, EW);
    gemm(p_o, CA, 0, Wo, CA, 0, p_amid, CA, 0, NT, CA, CA, 1, bo, 1.f, 0);
    gemm(s, CS, 0, Wlast, CA, 0, p_swl, CA, 0, NT, CA, CS, 1, blast, 1.f, 0);
    attnout_k<<<EWB, 256>>>(p_swl, p_amid, a, p_attn, EW);

    // adaLN 2 + SwiGLU transition
    ln_rows_k<<<NT, 256>>>(p_attn, p_aln2, nullptr, nullptr, CA);
    ln_rows_k<<<NT, 256>>>(s, p_sln2, a2_g, a2_b, CS);
    gemm(p_sln2, CS, 0, a2_sgW, CA, 0, p_t1, CA, 0, NT, CA, CS, 1, nullptr, 1.f, 0);
    gemm(p_sln2, CS, 0, a2_sbW, CA, 0, p_t2, CA, 0, NT, CA, CS, 1, nullptr, 1.f, 0);
    combine_adaln_k<<<EWB, 256>>>(p_t1, a2_sgb, p_t2, p_aln2, p_x, EW, CA);
    gemm(p_x, CA, 0, W1, 2 * CA, 0, p_ff1, 2 * CA, 0, NT, 2 * CA, CA, 1, nullptr, 1.f, 0);
    gemm(p_x, CA, 0, W2, 2 * CA, 0, p_ff2, 2 * CA, 0, NT, 2 * CA, CA, 1, nullptr, 1.f, 0);
    swiglu_k<<<(NT * 2 * CA + 255) / 256, 256>>>(p_ff1, p_ff2, NT * 2 * CA);
    gemm(p_ff1, 2 * CA, 0, Wb, CA, 0, p_bb, CA, 0, NT, CA, 2 * CA, 1, nullptr, 1.f, 0);
    gemm(s, CS, 0, Ws, CA, 0, p_sws, CA, 0, NT, CA, CS, 1, bs, 1.f, 0);
    final_k<<<EWB, 256>>>(p_sws, p_bb, p_attn, out_a, EW);
}

// round 14
// speedup vs baseline: 1.0018x; 1.0018x over previous
#include <cuda_runtime.h>
#include <stdint.h>
#include <math.h>

#define NT 1024
#define CA 768
#define CS 384
#define CZ 128
#define NH 16
#define HD 48
#define LNEPS 1e-5f

// ---------------- scratch (static device globals; no runtime allocation) ----------------
__device__ float g_sln1[NT*CS];
__device__ float g_sln2[NT*CS];
__device__ float g_aln [NT*CA];
__device__ float g_t1  [NT*CA];
__device__ float g_t2  [NT*CA];
__device__ float g_x   [NT*CA];
__device__ float g_q   [NT*CA];
__device__ float g_k   [NT*CA];
__device__ float g_v   [NT*CA];
__device__ float g_g   [NT*CA];
__device__ float g_kT  [NH*HD*NT];
__device__ float g_scores[(long)NH*NT*NT];
__device__ float g_o   [NT*CA];
__device__ float g_amid[NT*CA];
__device__ float g_swl [NT*CA];
__device__ float g_attn[NT*CA];
__device__ float g_aln2[NT*CA];
__device__ float g_ff1 [NT*2*CA];
__device__ float g_ff2 [NT*2*CA];
__device__ float g_bb  [NT*CA];
__device__ float g_sws [NT*CA];

__device__ __forceinline__ float wsum(float v){
    v += __shfl_xor_sync(0xffffffffu, v, 16);
    v += __shfl_xor_sync(0xffffffffu, v, 8);
    v += __shfl_xor_sync(0xffffffffu, v, 4);
    v += __shfl_xor_sync(0xffffffffu, v, 2);
    v += __shfl_xor_sync(0xffffffffu, v, 1);
    return v;
}
__device__ __forceinline__ float wmax(float v){
    v = fmaxf(v, __shfl_xor_sync(0xffffffffu, v, 16));
    v = fmaxf(v, __shfl_xor_sync(0xffffffffu, v, 8));
    v = fmaxf(v, __shfl_xor_sync(0xffffffffu, v, 4));
    v = fmaxf(v, __shfl_xor_sync(0xffffffffu, v, 2));
    v = fmaxf(v, __shfl_xor_sync(0xffffffffu, v, 1));
    return v;
}
__device__ __forceinline__ float sigm(float x){ return 1.0f/(1.0f + __expf(-x)); }

__device__ __forceinline__ void cpa16(unsigned dst, const float* src, int szbytes){
    asm volatile("cp.async.ca.shared.global [%0], [%1], 16, %2;"
                 :: "r"(dst), "l"(src), "r"(szbytes));
}
__device__ __forceinline__ void cpa_commit(){ asm volatile("cp.async.commit_group;"); }
template<int N_> __device__ __forceinline__ void cpa_wait(){
    asm volatile("cp.async.wait_group %0;" :: "n"(N_));
}

// ---------------- tf32 tensor-core GEMM: C = alpha*(A@B + bias) (+C) ----------------
// Block tile 128xBN x16, 8 warps, cp.async 3-stage pipeline. A row-major [M,K],
// B row-major [K,N], C row-major [M,N], batched via grid.z.
// Requires: K%16==0, M%128==0, 16B-aligned A/B bases, lda/ldb%4==0. N guarded.
// fp32 bits are fed to mma.tf32 directly (HW truncation).
#define SA 20
template<int BN>
__global__ __launch_bounds__(256) void tgemm_k(
    const float* __restrict__ A, int lda, long sA_,
    const float* __restrict__ B, int ldb, long sB_,
    float* __restrict__ C, int ldc, long sC_,
    int M, int N, int K,
    const float* __restrict__ bias, float alpha, int accum)
{
    constexpr int SBS = BN + 8;          // % 32 == 8 -> conflict-free fragment loads
    constexpr int WC  = BN / 32;         // warps along N
    constexpr int WTM = (WC == 4) ? 64 : 32;
    constexpr int MI  = WTM / 16;
    constexpr int ST  = 3;
    __shared__ float As[ST][128*SA];
    __shared__ float Bs[ST][16*SBS];

    int bz = blockIdx.z;
    A += (long)bz * sA_; B += (long)bz * sB_; C += (long)bz * sC_;
    int bm = blockIdx.y << 7, bn = blockIdx.x * BN;
    int tid = threadIdx.x;
    int lane = tid & 31, warp = tid >> 5;
    int wn = (warp % WC) * 32;
    int wm = (warp / WC) * WTM;
    int g = lane >> 2, tq = lane & 3;

    float acc[MI][4][4];
    #pragma unroll
    for (int mi = 0; mi < MI; mi++)
        #pragma unroll
        for (int nj = 0; nj < 4; nj++)
            #pragma unroll
            for (int r = 0; r < 4; r++) acc[mi][nj][r] = 0.0f;

    int KT = K >> 4;

    auto issue = [&](int s, int k0) {
        // A: 128 rows x 16 k = 512 float4, 2 per thread
        #pragma unroll
        for (int i = 0; i < 2; i++) {
            int idx = tid + (i << 8);
            int row = idx >> 2, kq = (idx & 3) << 2;
            unsigned dst = (unsigned)__cvta_generic_to_shared(&As[s][row*SA + kq]);
            cpa16(dst, A + (long)(bm + row) * lda + k0 + kq, 16);
        }
        // B: 16 rows x BN = BN*4 float4, BN/64 per thread
        #pragma unroll
        for (int i = 0; i < BN/64; i++) {
            int idx = tid + (i << 8);
            int row = idx / (BN/4), col = (idx % (BN/4)) << 2;
            unsigned dst = (unsigned)__cvta_generic_to_shared(&Bs[s][row*SBS + col]);
            cpa16(dst, B + (long)(k0 + row) * ldb + bn + col, (bn + col < N) ? 16 : 0);
        }
    };

    #pragma unroll
    for (int s = 0; s < ST-1; s++) {
        if (s < KT) issue(s, s << 4);
        cpa_commit();
    }

    for (int kt = 0; kt < KT; kt++) {
        cpa_wait<ST-2>();
        __syncthreads();
        int pre = kt + ST - 1;
        if (pre < KT) issue(pre % ST, pre << 4);
        cpa_commit();

        int buf = kt % ST;
        #pragma unroll
        for (int ks = 0; ks < 16; ks += 8) {
            unsigned af[MI][4], bf[4][2];
            #pragma unroll
            for (int mi = 0; mi < MI; mi++) {
                int m0 = (wm + (mi << 4) + g) * SA + ks + tq;
                af[mi][0] = __float_as_uint(As[buf][m0]);
                af[mi][1] = __float_as_uint(As[buf][m0 + 8*SA]);
                af[mi][2] = __float_as_uint(As[buf][m0 + 4]);
                af[mi][3] = __float_as_uint(As[buf][m0 + 8*SA + 4]);
            }
            #pragma unroll
            for (int nj = 0; nj < 4; nj++) {
                int n0 = (ks + tq) * SBS + wn + (nj << 3) + g;
                bf[nj][0] = __float_as_uint(Bs[buf][n0]);
                bf[nj][1] = __float_as_uint(Bs[buf][n0 + 4*SBS]);
            }
            #pragma unroll
            for (int mi = 0; mi < MI; mi++)
                #pragma unroll
                for (int nj = 0; nj < 4; nj++)
                    asm volatile(
                        "mma.sync.aligned.m16n8k8.row.col.f32.tf32.tf32.f32 "
                        "{%0,%1,%2,%3}, {%4,%5,%6,%7}, {%8,%9}, {%0,%1,%2,%3};"
                        : "+f"(acc[mi][nj][0]), "+f"(acc[mi][nj][1]),
                          "+f"(acc[mi][nj][2]), "+f"(acc[mi][nj][3])
                        : "r"(af[mi][0]), "r"(af[mi][1]), "r"(af[mi][2]), "r"(af[mi][3]),
                          "r"(bf[nj][0]), "r"(bf[nj][1]));
        }
    }

    #pragma unroll
    for (int mi = 0; mi < MI; mi++) {
        int r0 = bm + wm + (mi << 4) + g;
        int r1 = r0 + 8;
        #pragma unroll
        for (int nj = 0; nj < 4; nj++) {
            int col = bn + wn + (nj << 3) + (tq << 1);
            #pragma unroll
            for (int half = 0; half < 2; half++) {
                int cc = col + half;
                if (cc >= N) continue;
                float bia = bias ? bias[cc] : 0.0f;
                {
                    float v = (acc[mi][nj][half] + bia) * alpha;
                    long ci = (long)r0 * ldc + cc;
                    if (accum) v += C[ci];
                    C[ci] = v;
                }
                {
                    float v = (acc[mi][nj][2+half] + bia) * alpha;
                    long ci = (long)r1 * ldc + cc;
                    if (accum) v += C[ci];
                    C[ci] = v;
                }
            }
        }
    }
}

// ---------------- row LayerNorm (optional affine) ----------------
__global__ __launch_bounds__(256) void ln_rows_k(
    const float* __restrict__ in, float* __restrict__ out,
    const float* __restrict__ gam, const float* __restrict__ bet, int cols)
{
    long row = blockIdx.x;
    const float* x = in + row * cols;
    float* y = out + row * cols;
    float s1 = 0.f, s2 = 0.f;
    for (int c = threadIdx.x; c < cols; c += blockDim.x) {
        float v = x[c]; s1 += v; s2 += v * v;
    }
    __shared__ float r1[8], r2[8];
    int w = threadIdx.x >> 5, l = threadIdx.x & 31;
    s1 = wsum(s1); s2 = wsum(s2);
    if (l == 0) { r1[w] = s1; r2[w] = s2; }
    __syncthreads();
    __shared__ float sm, si;
    if (threadIdx.x == 0) {
        float a = 0.f, b = 0.f;
        int nw = blockDim.x >> 5;
        for (int i = 0; i < nw; i++) { a += r1[i]; b += r2[i]; }
        float mean = a / cols;
        float var = b / cols - mean * mean;
        sm = mean; si = rsqrtf(var + LNEPS);
    }
    __syncthreads();
    float mean = sm, inv = si;
    for (int c = threadIdx.x; c < cols; c += blockDim.x) {
        float v = (x[c] - mean) * inv;
        if (gam) v = v * gam[c] + bet[c];
        y[c] = v;
    }
}

// ---------------- fused z: LN + Wz projection -> scores bias, plus z copy-out ----------------
__global__ __launch_bounds__(256) void z_fused_k(
    const float* __restrict__ z, const float* __restrict__ zg, const float* __restrict__ zb,
    const float* __restrict__ Wz, float* __restrict__ scores, float* __restrict__ out_z)
{
    __shared__ float sW[NH * CZ];      // transposed: sW[h*128 + c]
    __shared__ float sg[CZ], sb[CZ];
    __shared__ float sbias[NH][8];
    int tid = threadIdx.x;
    for (int i = tid; i < NH * CZ; i += 256) {
        int c = i >> 4, h = i & 15;          // Wz is [128,16] row-major: Wz[c*16+h]
        sW[h * CZ + c] = Wz[i];
    }
    if (tid < CZ) { sg[tid] = zg[tid]; sb[tid] = zb[tid]; }
    __syncthreads();

    int w = tid >> 5, lane = tid & 31;
    long r = (long)blockIdx.x * 8 + w;       // z row index, r = q*1024 + kk
    const float* zr = z + r * CZ;
    int c0 = lane * 4;
    float4 xv = *(const float4*)(zr + c0);
    float s1 = xv.x + xv.y + xv.z + xv.w;
    float s2 = xv.x*xv.x + xv.y*xv.y + xv.z*xv.z + xv.w*xv.w;
    s1 = wsum(s1); s2 = wsum(s2);
    float mean = s1 * (1.0f / CZ);
    float inv = rsqrtf(s2 * (1.0f / CZ) - mean * mean + LNEPS);
    float y0 = (xv.x - mean) * inv * sg[c0+0] + sb[c0+0];
    float y1 = (xv.y - mean) * inv * sg[c0+1] + sb[c0+1];
    float y2 = (xv.z - mean) * inv * sg[c0+2] + sb[c0+2];
    float y3 = (xv.w - mean) * inv * sg[c0+3] + sb[c0+3];
    #pragma unroll
    for (int h = 0; h < NH; h++) {
        const float* wh = sW + h * CZ + c0;
        float p = y0*wh[0] + y1*wh[1] + y2*wh[2] + y3*wh[3];
        p = wsum(p);
        if (lane == 0) sbias[h][w] = p;
    }
    *(float4*)(out_z + r * CZ + c0) = xv;
    __syncthreads();
    if (tid < NH * 8) {
        int h = tid >> 3, wi = tid & 7;
        long rr = (long)blockIdx.x * 8 + wi;
        long q = rr >> 10, kk = rr & 1023;
        scores[((long)h * NT + q) * NT + kk] = sbias[h][wi];
    }
}

// ---------------- pack k -> kT[h][d][j] ----------------
__global__ void pack_kT_k(const float* __restrict__ k, float* __restrict__ kT) {
    int idx = blockIdx.x * blockDim.x + threadIdx.x;
    if (idx < NH * HD * NT) {
        int j = idx & (NT - 1);
        int d = (idx >> 10) % HD;
        int h = idx / (HD * NT);
        kT[idx] = k[(long)j * CA + h * HD + d];
    }
}

// ---------------- softmax over last dim (1024), in-place ----------------
__global__ __launch_bounds__(256) void softmax_k(float* __restrict__ sc) {
    long row = blockIdx.x;
    float* p = sc + row * NT;
    float4 v = *(float4*)(p + threadIdx.x * 4);
    float m = fmaxf(fmaxf(v.x, v.y), fmaxf(v.z, v.w));
    __shared__ float r[8];
    int w = threadIdx.x >> 5, l = threadIdx.x & 31;
    m = wmax(m);
    if (l == 0) r[w] = m;
    __syncthreads();
    __shared__ float bm, bs;
    if (threadIdx.x == 0) {
        float mm = r[0];
        for (int i = 1; i < 8; i++) mm = fmaxf(mm, r[i]);
        bm = mm;
    }
    __syncthreads();
    m = bm;
    float e0 = __expf(v.x - m), e1 = __expf(v.y - m), e2 = __expf(v.z - m), e3 = __expf(v.w - m);
    float s = e0 + e1 + e2 + e3;
    s = wsum(s);
    if (l == 0) r[w] = s;
    __syncthreads();
    if (threadIdx.x == 0) {
        float ss = 0.f;
        for (int i = 0; i < 8; i++) ss += r[i];
        bs = 1.0f / ss;
    }
    __syncthreads();
    float inv = bs;
    *(float4*)(p + threadIdx.x * 4) = make_float4(e0*inv, e1*inv, e2*inv, e3*inv);
}

// ---------------- elementwise kernels ----------------
__global__ void combine_adaln_k(const float* __restrict__ g1, const float* __restrict__ gb,
                                const float* __restrict__ g2, const float* __restrict__ aln,
                                float* __restrict__ out, int total, int cols) {
    int i = blockIdx.x * blockDim.x + threadIdx.x;
    if (i < total) {
        int c = i % cols;
        out[i] = sigm(g1[i] + gb[c]) * aln[i] + g2[i];
    }
}
__global__ void gate_k(float* __restrict__ o, const float* __restrict__ g, int total) {
    int i = blockIdx.x * blockDim.x + threadIdx.x;
    if (i < total) o[i] *= sigm(g[i]);
}
__global__ void attnout_k(const float* __restrict__ swl, const float* __restrict__ amid,
                          const float* __restrict__ a, float* __restrict__ out, int total) {
    int i = blockIdx.x * blockDim.x + threadIdx.x;
    if (i < total) out[i] = sigm(swl[i]) * amid[i] + a[i];
}
__global__ void swiglu_k(float* __restrict__ f1, const float* __restrict__ f2, int total) {
    int i = blockIdx.x * blockDim.x + threadIdx.x;
    if (i < total) {
        float v = f1[i];
        f1[i] = v * sigm(v) * f2[i];
    }
}
__global__ void final_k(const float* __restrict__ sws, const float* __restrict__ bb,
                        const float* __restrict__ attn, float* __restrict__ out, int total) {
    int i = blockIdx.x * blockDim.x + threadIdx.x;
    if (i < total) out[i] = sigm(sws[i]) * bb[i] + attn[i];
}

// ---------------- host ----------------
static void gemm(const float* A, int lda, long sA_, const float* B, int ldb, long sB_,
                 float* C, int ldc, long sC_, int M, int N, int K, int batch,
                 const float* bias, float alpha, int accum) {
    int my = (M + 127) / 128;
    if (N % 128 == 0 && (long)(N / 128) * my * batch >= 120) {
        dim3 grid(N / 128, my, batch);
        tgemm_k<128><<<grid, 256>>>(A, lda, sA_, B, ldb, sB_, C, ldc, sC_, M, N, K, bias, alpha, accum);
    } else {
        dim3 grid((N + 63) / 64, my, batch);
        tgemm_k<64><<<grid, 256>>>(A, lda, sA_, B, ldb, sB_, C, ldc, sC_, M, N, K, bias, alpha, accum);
    }
}

extern "C" void kernel_launch(void* const* d_in, const int* in_sizes, int n_in,
                              void* d_out, int out_size) {
    const float* a      = (const float*)d_in[0];
    const float* s      = (const float*)d_in[1];
    const float* z      = (const float*)d_in[2];
    const float* a1_g   = (const float*)d_in[3];
    const float* a1_b   = (const float*)d_in[4];
    const float* a1_sgW = (const float*)d_in[5];
    const float* a1_sgb = (const float*)d_in[6];
    const float* a1_sbW = (const float*)d_in[7];
    const float* Wq     = (const float*)d_in[8];
    const float* bq     = (const float*)d_in[9];
    const float* Wk     = (const float*)d_in[10];
    const float* Wv     = (const float*)d_in[11];
    const float* Wg     = (const float*)d_in[12];
    const float* Wo     = (const float*)d_in[13];
    const float* bo     = (const float*)d_in[14];
    const float* zg     = (const float*)d_in[15];
    const float* zb     = (const float*)d_in[16];
    const float* Wz     = (const float*)d_in[17];
    const float* Wlast  = (const float*)d_in[18];
    const float* blast  = (const float*)d_in[19];
    const float* a2_g   = (const float*)d_in[20];
    const float* a2_b   = (const float*)d_in[21];
    const float* a2_sgW = (const float*)d_in[22];
    const float* a2_sgb = (const float*)d_in[23];
    const float* a2_sbW = (const float*)d_in[24];
    const float* W1     = (const float*)d_in[25];
    const float* W2     = (const float*)d_in[26];
    const float* Wb     = (const float*)d_in[27];
    const float* Ws     = (const float*)d_in[28];
    const float* bs     = (const float*)d_in[29];

    float* out   = (float*)d_out;
    float* out_a = out;                                  // 1024*768
    float* out_s = out + NT * CA;                        // 1024*384
    float* out_z = out + NT * CA + NT * CS;              // 1024*1024*128

    float *p_sln1, *p_sln2, *p_aln, *p_t1, *p_t2, *p_x, *p_q, *p_k, *p_v, *p_g;
    float *p_kT, *p_scores, *p_o, *p_amid, *p_swl, *p_attn, *p_aln2, *p_ff1, *p_ff2, *p_bb, *p_sws;
    cudaGetSymbolAddress((void**)&p_sln1, g_sln1);
    cudaGetSymbolAddress((void**)&p_sln2, g_sln2);
    cudaGetSymbolAddress((void**)&p_aln,  g_aln);
    cudaGetSymbolAddress((void**)&p_t1,   g_t1);
    cudaGetSymbolAddress((void**)&p_t2,   g_t2);
    cudaGetSymbolAddress((void**)&p_x,    g_x);
    cudaGetSymbolAddress((void**)&p_q,    g_q);
    cudaGetSymbolAddress((void**)&p_k,    g_k);
    cudaGetSymbolAddress((void**)&p_v,    g_v);
    cudaGetSymbolAddress((void**)&p_g,    g_g);
    cudaGetSymbolAddress((void**)&p_kT,   g_kT);
    cudaGetSymbolAddress((void**)&p_scores, g_scores);
    cudaGetSymbolAddress((void**)&p_o,    g_o);
    cudaGetSymbolAddress((void**)&p_amid, g_amid);
    cudaGetSymbolAddress((void**)&p_swl,  g_swl);
    cudaGetSymbolAddress((void**)&p_attn, g_attn);
    cudaGetSymbolAddress((void**)&p_aln2, g_aln2);
    cudaGetSymbolAddress((void**)&p_ff1,  g_ff1);
    cudaGetSymbolAddress((void**)&p_ff2,  g_ff2);
    cudaGetSymbolAddress((void**)&p_bb,   g_bb);
    cudaGetSymbolAddress((void**)&p_sws,  g_sws);

    const int EW = NT * CA;            // 786432
    const int EWB = (EW + 255) / 256;
    const float qscale = rsqrtf((float)HD);

    // pair bias + z passthrough (memory-bound; launch first)
    z_fused_k<<<(NT * NT) / 8, 256>>>(z, zg, zb, Wz, p_scores, out_z);
    cudaMemcpyAsync(out_s, s, (size_t)NT * CS * sizeof(float), cudaMemcpyDeviceToDevice, 0);

    // adaLN 1
    ln_rows_k<<<NT, 256>>>(s, p_sln1, a1_g, a1_b, CS);
    ln_rows_k<<<NT, 256>>>(a, p_aln, nullptr, nullptr, CA);
    gemm(p_sln1, CS, 0, a1_sgW, CA, 0, p_t1, CA, 0, NT, CA, CS, 1, nullptr, 1.f, 0);
    gemm(p_sln1, CS, 0, a1_sbW, CA, 0, p_t2, CA, 0, NT, CA, CS, 1, nullptr, 1.f, 0);
    combine_adaln_k<<<EWB, 256>>>(p_t1, a1_sgb, p_t2, p_aln, p_x, EW, CA);

    // projections
    gemm(p_x, CA, 0, Wq, CA, 0, p_q, CA, 0, NT, CA, CA, 1, bq, qscale, 0);
    gemm(p_x, CA, 0, Wk, CA, 0, p_k, CA, 0, NT, CA, CA, 1, nullptr, 1.f, 0);
    gemm(p_x, CA, 0, Wv, CA, 0, p_v, CA, 0, NT, CA, CA, 1, nullptr, 1.f, 0);
    gemm(p_x, CA, 0, Wg, CA, 0, p_g, CA, 0, NT, CA, CA, 1, nullptr, 1.f, 0);
    pack_kT_k<<<(NH * HD * NT + 255) / 256, 256>>>(p_k, p_kT);

    // attention: scores = q@kT + bias (bias already in scores), softmax, o = P@v
    gemm(p_q, CA, HD, p_kT, NT, (long)HD * NT, p_scores, NT, (long)NT * NT,
         NT, NT, HD, NH, nullptr, 1.f, 1);
    softmax_k<<<NH * NT, 256>>>(p_scores);
    gemm(p_scores, NT, (long)NT * NT, p_v, CA, HD, p_o, CA, HD,
         NT, HD, NT, NH, nullptr, 1.f, 0);
    gate_k<<<EWB, 256>>>(p_o, p_g, EW);
    gemm(p_o, CA, 0, Wo, CA, 0, p_amid, CA, 0, NT, CA, CA, 1, bo, 1.f, 0);
    gemm(s, CS, 0, Wlast, CA, 0, p_swl, CA, 0, NT, CA, CS, 1, blast, 1.f, 0);
    attnout_k<<<EWB, 256>>>(p_swl, p_amid, a, p_attn, EW);

    // adaLN 2 + SwiGLU transition
    ln_rows_k<<<NT, 256>>>(p_attn, p_aln2, nullptr, nullptr, CA);
    ln_rows_k<<<NT, 256>>>(s, p_sln2, a2_g, a2_b, CS);
    gemm(p_sln2, CS, 0, a2_sgW, CA, 0, p_t1, CA, 0, NT, CA, CS, 1, nullptr, 1.f, 0);
    gemm(p_sln2, CS, 0, a2_sbW, CA, 0, p_t2, CA, 0, NT, CA, CS, 1, nullptr, 1.f, 0);
    combine_adaln_k<<<EWB, 256>>>(p_t1, a2_sgb, p_t2, p_aln2, p_x, EW, CA);
    gemm(p_x, CA, 0, W1, 2 * CA, 0, p_ff1, 2 * CA, 0, NT, 2 * CA, CA, 1, nullptr, 1.f, 0);
    gemm(p_x, CA, 0, W2, 2 * CA, 0, p_ff2, 2 * CA, 0, NT, 2 * CA, CA, 1, nullptr, 1.f, 0);
    swiglu_k<<<(NT * 2 * CA + 255) / 256, 256>>>(p_ff1, p_ff2, NT * 2 * CA);
    gemm(p_ff1, 2 * CA, 0, Wb, CA, 0, p_bb, CA, 0, NT, CA, 2 * CA, 1, nullptr, 1.f, 0);
    gemm(s, CS, 0, Ws, CA, 0, p_sws, CA, 0, NT, CA, CS, 1, bs, 1.f, 0);
    final_k<<<EWB, 256>>>(p_sws, p_bb, p_attn, out_a, EW);
}

// round 15
// speedup vs baseline: 1.0026x; 1.0008x over previous
#include <cuda_runtime.h>
#include <stdint.h>
#include <math.h>

#define NT 1024
#define CA 768
#define CS 384
#define CZ 128
#define NH 16
#define HD 48
#define LNEPS 1e-5f

// ---------------- scratch (static device globals; no runtime allocation) ----------------
__device__ float g_sln1[NT*CS];
__device__ float g_sln2[NT*CS];
__device__ float g_aln [NT*CA];
__device__ float g_t1  [NT*CA];
__device__ float g_t2  [NT*CA];
__device__ float g_x   [NT*CA];
__device__ float g_q   [NT*CA];
__device__ float g_k   [NT*CA];
__device__ float g_v   [NT*CA];
__device__ float g_g   [NT*CA];
__device__ float g_kT  [NH*HD*NT];
__device__ float g_scores[(long)NH*NT*NT];
__device__ float g_o   [NT*CA];
__device__ float g_amid[NT*CA];
__device__ float g_swl [NT*CA];
__device__ float g_attn[NT*CA];
__device__ float g_aln2[NT*CA];
__device__ float g_ff1 [NT*2*CA];
__device__ float g_ff2 [NT*2*CA];
__device__ float g_bb  [NT*CA];
__device__ float g_sws [NT*CA];

__device__ __forceinline__ float wsum(float v){
    v += __shfl_xor_sync(0xffffffffu, v, 16);
    v += __shfl_xor_sync(0xffffffffu, v, 8);
    v += __shfl_xor_sync(0xffffffffu, v, 4);
    v += __shfl_xor_sync(0xffffffffu, v, 2);
    v += __shfl_xor_sync(0xffffffffu, v, 1);
    return v;
}
__device__ __forceinline__ float wmax(float v){
    v = fmaxf(v, __shfl_xor_sync(0xffffffffu, v, 16));
    v = fmaxf(v, __shfl_xor_sync(0xffffffffu, v, 8));
    v = fmaxf(v, __shfl_xor_sync(0xffffffffu, v, 4));
    v = fmaxf(v, __shfl_xor_sync(0xffffffffu, v, 2));
    v = fmaxf(v, __shfl_xor_sync(0xffffffffu, v, 1));
    return v;
}
__device__ __forceinline__ float sigm(float x){ return 1.0f/(1.0f + __expf(-x)); }

__device__ __forceinline__ void cpa16(unsigned dst, const float* src, int szbytes){
    asm volatile("cp.async.ca.shared.global [%0], [%1], 16, %2;"
                 :: "r"(dst), "l"(src), "r"(szbytes));
}
__device__ __forceinline__ void cpa_commit(){ asm volatile("cp.async.commit_group;"); }
template<int N_> __device__ __forceinline__ void cpa_wait(){
    asm volatile("cp.async.wait_group %0;" :: "n"(N_));
}

// ---------------- tf32 tensor-core GEMM: C = alpha*(A@B + bias) (+C) ----------------
// Block tile 128xBN x16, 8 warps, cp.async 3-stage pipeline. A row-major [M,K],
// B row-major [K,N], C row-major [M,N], batched via grid.z.
// Requires: K%16==0, M%128==0, 16B-aligned A/B bases, lda/ldb%4==0. N guarded.
// fp32 bits are fed to mma.tf32 directly (HW truncation).
#define SA 20
template<int BN>
__global__ __launch_bounds__(256) void tgemm_k(
    const float* __restrict__ A, int lda, long sA_,
    const float* __restrict__ B, int ldb, long sB_,
    float* __restrict__ C, int ldc, long sC_,
    int M, int N, int K,
    const float* __restrict__ bias, float alpha, int accum)
{
    constexpr int SBS = BN + 8;          // % 32 == 8 -> conflict-free fragment loads
    constexpr int WC  = BN / 32;         // warps along N
    constexpr int WTM = (WC == 4) ? 64 : 32;
    constexpr int MI  = WTM / 16;
    constexpr int ST  = 3;
    __shared__ float As[ST][128*SA];
    __shared__ float Bs[ST][16*SBS];

    int bz = blockIdx.z;
    A += (long)bz * sA_; B += (long)bz * sB_; C += (long)bz * sC_;
    int bm = blockIdx.y << 7, bn = blockIdx.x * BN;
    int tid = threadIdx.x;
    int lane = tid & 31, warp = tid >> 5;
    int wn = (warp % WC) * 32;
    int wm = (warp / WC) * WTM;
    int g = lane >> 2, tq = lane & 3;

    float acc[MI][4][4];
    #pragma unroll
    for (int mi = 0; mi < MI; mi++)
        #pragma unroll
        for (int nj = 0; nj < 4; nj++)
            #pragma unroll
            for (int r = 0; r < 4; r++) acc[mi][nj][r] = 0.0f;

    int KT = K >> 4;

    auto issue = [&](int s, int k0) {
        // A: 128 rows x 16 k = 512 float4, 2 per thread
        #pragma unroll
        for (int i = 0; i < 2; i++) {
            int idx = tid + (i << 8);
            int row = idx >> 2, kq = (idx & 3) << 2;
            unsigned dst = (unsigned)__cvta_generic_to_shared(&As[s][row*SA + kq]);
            cpa16(dst, A + (long)(bm + row) * lda + k0 + kq, 16);
        }
        // B: 16 rows x BN = BN*4 float4, BN/64 per thread
        #pragma unroll
        for (int i = 0; i < BN/64; i++) {
            int idx = tid + (i << 8);
            int row = idx / (BN/4), col = (idx % (BN/4)) << 2;
            unsigned dst = (unsigned)__cvta_generic_to_shared(&Bs[s][row*SBS + col]);
            cpa16(dst, B + (long)(k0 + row) * ldb + bn + col, (bn + col < N) ? 16 : 0);
        }
    };

    #pragma unroll
    for (int s = 0; s < ST-1; s++) {
        if (s < KT) issue(s, s << 4);
        cpa_commit();
    }

    for (int kt = 0; kt < KT; kt++) {
        cpa_wait<ST-2>();
        __syncthreads();
        int pre = kt + ST - 1;
        if (pre < KT) issue(pre % ST, pre << 4);
        cpa_commit();

        int buf = kt % ST;
        #pragma unroll
        for (int ks = 0; ks < 16; ks += 8) {
            unsigned af[MI][4], bf[4][2];
            #pragma unroll
            for (int mi = 0; mi < MI; mi++) {
                int m0 = (wm + (mi << 4) + g) * SA + ks + tq;
                af[mi][0] = __float_as_uint(As[buf][m0]);
                af[mi][1] = __float_as_uint(As[buf][m0 + 8*SA]);
                af[mi][2] = __float_as_uint(As[buf][m0 + 4]);
                af[mi][3] = __float_as_uint(As[buf][m0 + 8*SA + 4]);
            }
            #pragma unroll
            for (int nj = 0; nj < 4; nj++) {
                int n0 = (ks + tq) * SBS + wn + (nj << 3) + g;
                bf[nj][0] = __float_as_uint(Bs[buf][n0]);
                bf[nj][1] = __float_as_uint(Bs[buf][n0 + 4*SBS]);
            }
            #pragma unroll
            for (int mi = 0; mi < MI; mi++)
                #pragma unroll
                for (int nj = 0; nj < 4; nj++)
                    asm volatile(
                        "mma.sync.aligned.m16n8k8.row.col.f32.tf32.tf32.f32 "
                        "{%0,%1,%2,%3}, {%4,%5,%6,%7}, {%8,%9}, {%0,%1,%2,%3};"
                        : "+f"(acc[mi][nj][0]), "+f"(acc[mi][nj][1]),
                          "+f"(acc[mi][nj][2]), "+f"(acc[mi][nj][3])
                        : "r"(af[mi][0]), "r"(af[mi][1]), "r"(af[mi][2]), "r"(af[mi][3]),
                          "r"(bf[nj][0]), "r"(bf[nj][1]));
        }
    }

    #pragma unroll
    for (int mi = 0; mi < MI; mi++) {
        int r0 = bm + wm + (mi << 4) + g;
        int r1 = r0 + 8;
        #pragma unroll
        for (int nj = 0; nj < 4; nj++) {
            int col = bn + wn + (nj << 3) + (tq << 1);
            #pragma unroll
            for (int half = 0; half < 2; half++) {
                int cc = col + half;
                if (cc >= N) continue;
                float bia = bias ? bias[cc] : 0.0f;
                {
                    float v = (acc[mi][nj][half] + bia) * alpha;
                    long ci = (long)r0 * ldc + cc;
                    if (accum) v += C[ci];
                    C[ci] = v;
                }
                {
                    float v = (acc[mi][nj][2+half] + bia) * alpha;
                    long ci = (long)r1 * ldc + cc;
                    if (accum) v += C[ci];
                    C[ci] = v;
                }
            }
        }
    }
}

// ---------------- row LayerNorm (optional affine) ----------------
__global__ __launch_bounds__(256) void ln_rows_k(
    const float* __restrict__ in, float* __restrict__ out,
    const float* __restrict__ gam, const float* __restrict__ bet, int cols)
{
    long row = blockIdx.x;
    const float* x = in + row * cols;
    float* y = out + row * cols;
    float s1 = 0.f, s2 = 0.f;
    for (int c = threadIdx.x; c < cols; c += blockDim.x) {
        float v = x[c]; s1 += v; s2 += v * v;
    }
    __shared__ float r1[8], r2[8];
    int w = threadIdx.x >> 5, l = threadIdx.x & 31;
    s1 = wsum(s1); s2 = wsum(s2);
    if (l == 0) { r1[w] = s1; r2[w] = s2; }
    __syncthreads();
    __shared__ float sm, si;
    if (threadIdx.x == 0) {
        float a = 0.f, b = 0.f;
        int nw = blockDim.x >> 5;
        for (int i = 0; i < nw; i++) { a += r1[i]; b += r2[i]; }
        float mean = a / cols;
        float var = b / cols - mean * mean;
        sm = mean; si = rsqrtf(var + LNEPS);
    }
    __syncthreads();
    float mean = sm, inv = si;
    for (int c = threadIdx.x; c < cols; c += blockDim.x) {
        float v = (x[c] - mean) * inv;
        if (gam) v = v * gam[c] + bet[c];
        y[c] = v;
    }
}

// ---------------- fused z: LN + Wz projection -> scores bias, plus z copy-out ----------------
__global__ __launch_bounds__(256) void z_fused_k(
    const float* __restrict__ z, const float* __restrict__ zg, const float* __restrict__ zb,
    const float* __restrict__ Wz, float* __restrict__ scores, float* __restrict__ out_z)
{
    __shared__ float sW[NH * CZ];      // transposed: sW[h*128 + c]
    __shared__ float sg[CZ], sb[CZ];
    __shared__ float sbias[NH][8];
    int tid = threadIdx.x;
    for (int i = tid; i < NH * CZ; i += 256) {
        int c = i >> 4, h = i & 15;          // Wz is [128,16] row-major: Wz[c*16+h]
        sW[h * CZ + c] = Wz[i];
    }
    if (tid < CZ) { sg[tid] = zg[tid]; sb[tid] = zb[tid]; }
    __syncthreads();

    int w = tid >> 5, lane = tid & 31;
    long r = (long)blockIdx.x * 8 + w;       // z row index, r = q*1024 + kk
    const float* zr = z + r * CZ;
    int c0 = lane * 4;
    float4 xv = *(const float4*)(zr + c0);
    float s1 = xv.x + xv.y + xv.z + xv.w;
    float s2 = xv.x*xv.x + xv.y*xv.y + xv.z*xv.z + xv.w*xv.w;
    s1 = wsum(s1); s2 = wsum(s2);
    float mean = s1 * (1.0f / CZ);
    float inv = rsqrtf(s2 * (1.0f / CZ) - mean * mean + LNEPS);
    float y0 = (xv.x - mean) * inv * sg[c0+0] + sb[c0+0];
    float y1 = (xv.y - mean) * inv * sg[c0+1] + sb[c0+1];
    float y2 = (xv.z - mean) * inv * sg[c0+2] + sb[c0+2];
    float y3 = (xv.w - mean) * inv * sg[c0+3] + sb[c0+3];
    #pragma unroll
    for (int h = 0; h < NH; h++) {
        const float* wh = sW + h * CZ + c0;
        float p = y0*wh[0] + y1*wh[1] + y2*wh[2] + y3*wh[3];
        p = wsum(p);
        if (lane == 0) sbias[h][w] = p;
    }
    *(float4*)(out_z + r * CZ + c0) = xv;
    __syncthreads();
    if (tid < NH * 8) {
        int h = tid >> 3, wi = tid & 7;
        long rr = (long)blockIdx.x * 8 + wi;
        long q = rr >> 10, kk = rr & 1023;
        scores[((long)h * NT + q) * NT + kk] = sbias[h][wi];
    }
}

// ---------------- pack k -> kT[h][d][j] ----------------
__global__ void pack_kT_k(const float* __restrict__ k, float* __restrict__ kT) {
    int idx = blockIdx.x * blockDim.x + threadIdx.x;
    if (idx < NH * HD * NT) {
        int j = idx & (NT - 1);
        int d = (idx >> 10) % HD;
        int h = idx / (HD * NT);
        kT[idx] = k[(long)j * CA + h * HD + d];
    }
}

// ---------------- softmax over last dim (1024), in-place ----------------
__global__ __launch_bounds__(256) void softmax_k(float* __restrict__ sc) {
    long row = blockIdx.x;
    float* p = sc + row * NT;
    float4 v = *(float4*)(p + threadIdx.x * 4);
    float m = fmaxf(fmaxf(v.x, v.y), fmaxf(v.z, v.w));
    __shared__ float r[8];
    int w = threadIdx.x >> 5, l = threadIdx.x & 31;
    m = wmax(m);
    if (l == 0) r[w] = m;
    __syncthreads();
    __shared__ float bm, bs;
    if (threadIdx.x == 0) {
        float mm = r[0];
        for (int i = 1; i < 8; i++) mm = fmaxf(mm, r[i]);
        bm = mm;
    }
    __syncthreads();
    m = bm;
    float e0 = __expf(v.x - m), e1 = __expf(v.y - m), e2 = __expf(v.z - m), e3 = __expf(v.w - m);
    float s = e0 + e1 + e2 + e3;
    s = wsum(s);
    if (l == 0) r[w] = s;
    __syncthreads();
    if (threadIdx.x == 0) {
        float ss = 0.f;
        for (int i = 0; i < 8; i++) ss += r[i];
        bs = 1.0f / ss;
    }
    __syncthreads();
    float inv = bs;
    *(float4*)(p + threadIdx.x * 4) = make_float4(e0*inv, e1*inv, e2*inv, e3*inv);
}

// ---------------- elementwise kernels ----------------
__global__ void combine_adaln_k(const float* __restrict__ g1, const float* __restrict__ gb,
                                const float* __restrict__ g2, const float* __restrict__ aln,
                                float* __restrict__ out, int total, int cols) {
    int i = blockIdx.x * blockDim.x + threadIdx.x;
    if (i < total) {
        int c = i % cols;
        out[i] = sigm(g1[i] + gb[c]) * aln[i] + g2[i];
    }
}
__global__ void gate_k(float* __restrict__ o, const float* __restrict__ g, int total) {
    int i = blockIdx.x * blockDim.x + threadIdx.x;
    if (i < total) o[i] *= sigm(g[i]);
}
__global__ void attnout_k(const float* __restrict__ swl, const float* __restrict__ amid,
                          const float* __restrict__ a, float* __restrict__ out, int total) {
    int i = blockIdx.x * blockDim.x + threadIdx.x;
    if (i < total) out[i] = sigm(swl[i]) * amid[i] + a[i];
}
__global__ void swiglu_k(float* __restrict__ f1, const float* __restrict__ f2, int total) {
    int i = blockIdx.x * blockDim.x + threadIdx.x;
    if (i < total) {
        float v = f1[i];
        f1[i] = v * sigm(v) * f2[i];
    }
}
__global__ void final_k(const float* __restrict__ sws, const float* __restrict__ bb,
                        const float* __restrict__ attn, float* __restrict__ out, int total) {
    int i = blockIdx.x * blockDim.x + threadIdx.x;
    if (i < total) out[i] = sigm(sws[i]) * bb[i] + attn[i];
}

// ---------------- host ----------------
static void gemm(const float* A, int lda, long sA_, const float* B, int ldb, long sB_,
                 float* C, int ldc, long sC_, int M, int N, int K, int batch,
                 const float* bias, float alpha, int accum) {
    int my = (M + 127) / 128;
    if (N % 128 == 0 && (long)(N / 128) * my * batch >= 120) {
        dim3 grid(N / 128, my, batch);
        tgemm_k<128><<<grid, 256>>>(A, lda, sA_, B, ldb, sB_, C, ldc, sC_, M, N, K, bias, alpha, accum);
    } else {
        dim3 grid((N + 63) / 64, my, batch);
        tgemm_k<64><<<grid, 256>>>(A, lda, sA_, B, ldb, sB_, C, ldc, sC_, M, N, K, bias, alpha, accum);
    }
}

extern "C" void kernel_launch(void* const* d_in, const int* in_sizes, int n_in,
                              void* d_out, int out_size) {
    const float* a      = (const float*)d_in[0];
    const float* s      = (const float*)d_in[1];
    const float* z      = (const float*)d_in[2];
    const float* a1_g   = (const float*)d_in[3];
    const float* a1_b   = (const float*)d_in[4];
    const float* a1_sgW = (const float*)d_in[5];
    const float* a1_sgb = (const float*)d_in[6];
    const float* a1_sbW = (const float*)d_in[7];
    const float* Wq     = (const float*)d_in[8];
    const float* bq     = (const float*)d_in[9];
    const float* Wk     = (const float*)d_in[10];
    const float* Wv     = (const float*)d_in[11];
    const float* Wg     = (const float*)d_in[12];
    const float* Wo     = (const float*)d_in[13];
    const float* bo     = (const float*)d_in[14];
    const float* zg     = (const float*)d_in[15];
    const float* zb     = (const float*)d_in[16];
    const float* Wz     = (const float*)d_in[17];
    const float* Wlast  = (const float*)d_in[18];
    const float* blast  = (const float*)d_in[19];
    const float* a2_g   = (const float*)d_in[20];
    const float* a2_b   = (const float*)d_in[21];
    const float* a2_sgW = (const float*)d_in[22];
    const float* a2_sgb = (const float*)d_in[23];
    const float* a2_sbW = (const float*)d_in[24];
    const float* W1     = (const float*)d_in[25];
    const float* W2     = (const float*)d_in[26];
    const float* Wb     = (const float*)d_in[27];
    const float* Ws     = (const float*)d_in[28];
    const float* bs     = (const float*)d_in[29];

    float* out   = (float*)d_out;
    float* out_a = out;                                  // 1024*768
    float* out_s = out + NT * CA;                        // 1024*384
    float* out_z = out + NT * CA + NT * CS;              // 1024*1024*128

    float *p_sln1, *p_sln2, *p_aln, *p_t1, *p_t2, *p_x, *p_q, *p_k, *p_v, *p_g;
    float *p_kT, *p_scores, *p_o, *p_amid, *p_swl, *p_attn, *p_aln2, *p_ff1, *p_ff2, *p_bb, *p_sws;
    cudaGetSymbolAddress((void**)&p_sln1, g_sln1);
    cudaGetSymbolAddress((void**)&p_sln2, g_sln2);
    cudaGetSymbolAddress((void**)&p_aln,  g_aln);
    cudaGetSymbolAddress((void**)&p_t1,   g_t1);
    cudaGetSymbolAddress((void**)&p_t2,   g_t2);
    cudaGetSymbolAddress((void**)&p_x,    g_x);
    cudaGetSymbolAddress((void**)&p_q,    g_q);
    cudaGetSymbolAddress((void**)&p_k,    g_k);
    cudaGetSymbolAddress((void**)&p_v,    g_v);
    cudaGetSymbolAddress((void**)&p_g,    g_g);
    cudaGetSymbolAddress((void**)&p_kT,   g_kT);
    cudaGetSymbolAddress((void**)&p_scores, g_scores);
    cudaGetSymbolAddress((void**)&p_o,    g_o);
    cudaGetSymbolAddress((void**)&p_amid, g_amid);
    cudaGetSymbolAddress((void**)&p_swl,  g_swl);
    cudaGetSymbolAddress((void**)&p_attn, g_attn);
    cudaGetSymbolAddress((void**)&p_aln2, g_aln2);
    cudaGetSymbolAddress((void**)&p_ff1,  g_ff1);
    cudaGetSymbolAddress((void**)&p_ff2,  g_ff2);
    cudaGetSymbolAddress((void**)&p_bb,   g_bb);
    cudaGetSymbolAddress((void**)&p_sws,  g_sws);

    const int EW = NT * CA;            // 786432
    const int EWB = (EW + 255) / 256;
    const float qscale = rsqrtf((float)HD);

    // pair bias + z passthrough (memory-bound; launch first)
    z_fused_k<<<(NT * NT) / 8, 256>>>(z, zg, zb, Wz, p_scores, out_z);
    cudaMemcpyAsync(out_s, s, (size_t)NT * CS * sizeof(float), cudaMemcpyDeviceToDevice, 0);

    // adaLN 1
    ln_rows_k<<<NT, 256>>>(s, p_sln1, a1_g, a1_b, CS);
    ln_rows_k<<<NT, 256>>>(a, p_aln, nullptr, nullptr, CA);
    gemm(p_sln1, CS, 0, a1_sgW, CA, 0, p_t1, CA, 0, NT, CA, CS, 1, nullptr, 1.f, 0);
    gemm(p_sln1, CS, 0, a1_sbW, CA, 0, p_t2, CA, 0, NT, CA, CS, 1, nullptr, 1.f, 0);
    combine_adaln_k<<<EWB, 256>>>(p_t1, a1_sgb, p_t2, p_aln, p_x, EW, CA);

    // projections
    gemm(p_x, CA, 0, Wq, CA, 0, p_q, CA, 0, NT, CA, CA, 1, bq, qscale, 0);
    gemm(p_x, CA, 0, Wk, CA, 0, p_k, CA, 0, NT, CA, CA, 1, nullptr, 1.f, 0);
    gemm(p_x, CA, 0, Wv, CA, 0, p_v, CA, 0, NT, CA, CA, 1, nullptr, 1.f, 0);
    gemm(p_x, CA, 0, Wg, CA, 0, p_g, CA, 0, NT, CA, CA, 1, nullptr, 1.f, 0);
    pack_kT_k<<<(NH * HD * NT + 255) / 256, 256>>>(p_k, p_kT);

    // attention: scores = q@kT + bias (bias already in scores), softmax, o = P@v
    gemm(p_q, CA, HD, p_kT, NT, (long)HD * NT, p_scores, NT, (long)NT * NT,
         NT, NT, HD, NH, nullptr, 1.f, 1);
    softmax_k<<<NH * NT, 256>>>(p_scores);
    gemm(p_scores, NT, (long)NT * NT, p_v, CA, HD, p_o, CA, HD,
         NT, HD, NT, NH, nullptr, 1.f, 0);
    gate_k<<<EWB, 256>>>(p_o, p_g, EW);
    gemm(p_o, CA, 0, Wo, CA, 0, p_amid, CA, 0, NT, CA, CA, 1, bo, 1.f, 0);
    gemm(s, CS, 0, Wlast, CA, 0, p_swl, CA, 0, NT, CA, CS, 1, blast, 1.f, 0);
    attnout_k<<<EWB, 256>>>(p_swl, p_amid, a, p_attn, EW);

    // adaLN 2 + SwiGLU transition
    ln_rows_k<<<NT, 256>>>(p_attn, p_aln2, nullptr, nullptr, CA);
    ln_rows_k<<<NT, 256>>>(s, p_sln2, a2_g, a2_b, CS);
    gemm(p_sln2, CS, 0, a2_sgW, CA, 0, p_t1, CA, 0, NT, CA, CS, 1, nullptr, 1.f, 0);
    gemm(p_sln2, CS, 0, a2_sbW, CA, 0, p_t2, CA, 0, NT, CA, CS, 1, nullptr, 1.f, 0);
    combine_adaln_k<<<EWB, 256>>>(p_t1, a2_sgb, p_t2, p_aln2, p_x, EW, CA);
    gemm(p_x, CA, 0, W1, 2 * CA, 0, p_ff1, 2 * CA, 0, NT, 2 * CA, CA, 1, nullptr, 1.f, 0);
    gemm(p_x, CA, 0, W2, 2 * CA, 0, p_ff2, 2 * CA, 0, NT, 2 * CA, CA, 1, nullptr, 1.f, 0);
    swiglu_k<<<(NT * 2 * CA + 255) / 256, 256>>>(p_ff1, p_ff2, NT * 2 * CA);
    gemm(p_ff1, 2 * CA, 0, Wb, CA, 0, p_bb, CA, 0, NT, CA, 2 * CA, 1, nullptr, 1.f, 0);
    gemm(s, CS, 0, Ws, CA, 0, p_sws, CA, 0, NT, CA, CS, 1, bs, 1.f, 0);
    final_k<<<EWB, 256>>>(p_sws, p_bb, p_attn, out_a, EW);
}